// round 1
// baseline (speedup 1.0000x reference)
#include <cuda_runtime.h>
#include <cuda_bf16.h>
#include <cstdint>

// Shapes (fixed by the problem)
#define B_  4
#define T_  64
#define S_  256
#define E_  512   // encoder hidden
#define D_  512   // decoder hidden
#define F_  128   // field embed

#define LOG2E 1.4426950408889634f

// -------- scratch (device globals; no allocations allowed) --------
__device__ float g_out_hs [S_ * B_ * D_];   // tanh(enc @ W1^T + b1), flat rows (s*B+b)
__device__ float g_out_fds[B_ * S_ * D_];   // tanh(z   @ W3^T + b3), flat rows (b*S+s)
__device__ float g_o2p    [B_ * T_ * D_];   // tanh(out @ W2^T + b2) * log2e
__device__ float g_o3p    [B_ * T_ * D_];   // tanh(out @ W4^T + b4) * log2e

// ============================================================================
// GEMM: C[M,N] = post( A[M,K] @ Bm[N,K]^T + bias[N] )
//   post: tanh, optionally * log2e (MODE=1)
// Tiles: 64x64, BK=16, 256 threads, 4x4 per thread. M,N multiples of 64,
// K multiple of 16 (true for all four calls).
// ============================================================================
template <int MODE>
__global__ void __launch_bounds__(256)
gemm_nt_tanh(const float* __restrict__ A, const float* __restrict__ Bm,
             const float* __restrict__ bias, float* __restrict__ C,
             int M, int N, int K)
{
    const int BM = 64, BN = 64, BK = 16;
    __shared__ float As[BK][BM + 4];
    __shared__ float Bs[BK][BN + 4];

    int tid = threadIdx.x;
    int tx = tid & 15;        // 0..15 -> n sub
    int ty = tid >> 4;        // 0..15 -> m sub
    int m0 = blockIdx.y * BM;
    int n0 = blockIdx.x * BN;

    int lrow = tid >> 2;          // 0..63
    int lc4  = (tid & 3) * 4;     // 0,4,8,12

    float acc[4][4];
#pragma unroll
    for (int i = 0; i < 4; i++)
#pragma unroll
        for (int j = 0; j < 4; j++) acc[i][j] = 0.f;

    for (int k0 = 0; k0 < K; k0 += BK) {
        float4 av = *reinterpret_cast<const float4*>(&A [(size_t)(m0 + lrow) * K + k0 + lc4]);
        float4 bv = *reinterpret_cast<const float4*>(&Bm[(size_t)(n0 + lrow) * K + k0 + lc4]);
        __syncthreads();
        As[lc4 + 0][lrow] = av.x; As[lc4 + 1][lrow] = av.y;
        As[lc4 + 2][lrow] = av.z; As[lc4 + 3][lrow] = av.w;
        Bs[lc4 + 0][lrow] = bv.x; Bs[lc4 + 1][lrow] = bv.y;
        Bs[lc4 + 2][lrow] = bv.z; Bs[lc4 + 3][lrow] = bv.w;
        __syncthreads();
#pragma unroll
        for (int kk = 0; kk < BK; kk++) {
            float4 ar = *reinterpret_cast<const float4*>(&As[kk][ty * 4]);
            float4 br = *reinterpret_cast<const float4*>(&Bs[kk][tx * 4]);
            float a4[4] = {ar.x, ar.y, ar.z, ar.w};
            float b4[4] = {br.x, br.y, br.z, br.w};
#pragma unroll
            for (int i = 0; i < 4; i++)
#pragma unroll
                for (int j = 0; j < 4; j++)
                    acc[i][j] = fmaf(a4[i], b4[j], acc[i][j]);
        }
    }

    // epilogue
#pragma unroll
    for (int i = 0; i < 4; i++) {
        float4 v;
        float* vp = &v.x;
#pragma unroll
        for (int j = 0; j < 4; j++) {
            float c = acc[i][j] + bias[n0 + tx * 4 + j];
            c = tanhf(c);
            if (MODE == 1) c *= LOG2E;
            vp[j] = c;
        }
        *reinterpret_cast<float4*>(&C[(size_t)(m0 + ty * 4 + i) * N + n0 + tx * 4]) = v;
    }
}

// ============================================================================
// Fused dual-softmax attention.
//   gamma(s,d) = softmax_s( h*o2' + f*o3' )   (o2',o3' pre-scaled by log2e)
//   attn(b,t,d) = sum_s gamma * enc
// Block: 128 threads (one d each), handles T_TILE=8 decoder steps.
// Grid: x = d-chunk (4), y = t-tile (8), z = b (4)  -> 128 blocks.
// ============================================================================
__global__ void __launch_bounds__(128)
dual_attn_kernel(const float* __restrict__ out_hs,
                 const float* __restrict__ out_fds,
                 const float* __restrict__ enc,     // encoder_hidden flat [S*B, E]
                 const float* __restrict__ o2p,     // [B*T, D]
                 const float* __restrict__ o3p,     // [B*T, D]
                 const float* __restrict__ outp,    // output [B*T, D]
                 float* __restrict__ concat,        // [B*T, 2D]
                 float* __restrict__ attn_out)      // [B*T, D] or nullptr
{
    const int TT = 8;
    int d  = blockIdx.x * 128 + threadIdx.x;
    int t0 = blockIdx.y * TT;
    int b  = blockIdx.z;

    float o2[TT], o3[TT], s1[TT], s2[TT];
#pragma unroll
    for (int i = 0; i < TT; i++) {
        int r = b * T_ + t0 + i;
        o2[i] = o2p[r * D_ + d];
        o3[i] = o3p[r * D_ + d];
        s1[i] = 0.f;
        s2[i] = 0.f;
    }

    size_t base = (size_t)(b * S_) * D_ + d;
#pragma unroll 2
    for (int s = 0; s < S_; s++) {
        float h = out_hs [base];
        float f = out_fds[base];
        float e = enc    [base];
        base += D_;
#pragma unroll
        for (int i = 0; i < TT; i++) {
            float g = fmaf(h, o2[i], f * o3[i]);
            float ex;
            asm("ex2.approx.f32 %0, %1;" : "=f"(ex) : "f"(g));
            s1[i] += ex;
            s2[i] = fmaf(ex, e, s2[i]);
        }
    }

#pragma unroll
    for (int i = 0; i < TT; i++) {
        int r = b * T_ + t0 + i;
        float a = s2[i] / s1[i];
        concat[(size_t)r * (2 * D_) + d]      = outp[(size_t)r * D_ + d];
        concat[(size_t)r * (2 * D_) + D_ + d] = a;
        if (attn_out) attn_out[(size_t)r * D_ + d] = a;
    }
}

// ============================================================================
// kernel_launch
// Inputs (metadata order):
//  0 output [B,T,D]  1 encoder_hidden [S,B,E]  2 input_z [B,S,F]
//  3 W1 [D,E]  4 b1 [D]  5 W2 [D,D]  6 b2 [D]  7 W3 [D,F]  8 b3 [D]
//  9 W4 [D,D] 10 b4 [D]
// Output: concat [B,T,2D] (262144 f32) followed by attn [B,T,D] (131072 f32).
// ============================================================================
extern "C" void kernel_launch(void* const* d_in, const int* in_sizes, int n_in,
                              void* d_out, int out_size)
{
    const float* output = (const float*)d_in[0];
    const float* enc    = (const float*)d_in[1];
    const float* z      = (const float*)d_in[2];
    const float* W1 = (const float*)d_in[3];
    const float* b1 = (const float*)d_in[4];
    const float* W2 = (const float*)d_in[5];
    const float* b2 = (const float*)d_in[6];
    const float* W3 = (const float*)d_in[7];
    const float* b3 = (const float*)d_in[8];
    const float* W4 = (const float*)d_in[9];
    const float* b4 = (const float*)d_in[10];

    float *p_hs, *p_fds, *p_o2, *p_o3;
    cudaGetSymbolAddress((void**)&p_hs,  g_out_hs);
    cudaGetSymbolAddress((void**)&p_fds, g_out_fds);
    cudaGetSymbolAddress((void**)&p_o2,  g_o2p);
    cudaGetSymbolAddress((void**)&p_o3,  g_o3p);

    float* concat = (float*)d_out;
    const int concat_elems = B_ * T_ * 2 * D_;           // 262144
    const int attn_elems   = B_ * T_ * D_;               // 131072
    float* attn_out = (out_size >= concat_elems + attn_elems)
                        ? concat + concat_elems : nullptr;

    // lin1: [S*B=1024, E=512] @ W1[512,512]^T -> tanh
    gemm_nt_tanh<0><<<dim3(D_ / 64, (S_ * B_) / 64), 256>>>(enc, W1, b1, p_hs,  S_ * B_, D_, E_);
    // lin3: [B*S=1024, F=128] @ W3[512,128]^T -> tanh
    gemm_nt_tanh<0><<<dim3(D_ / 64, (B_ * S_) / 64), 256>>>(z,   W3, b3, p_fds, B_ * S_, D_, F_);
    // lin2/lin4: [B*T=256, D=512] @ W^T -> tanh * log2e
    gemm_nt_tanh<1><<<dim3(D_ / 64, (B_ * T_) / 64), 256>>>(output, W2, b2, p_o2, B_ * T_, D_, D_);
    gemm_nt_tanh<1><<<dim3(D_ / 64, (B_ * T_) / 64), 256>>>(output, W4, b4, p_o3, B_ * T_, D_, D_);

    // fused attention + concat
    dual_attn_kernel<<<dim3(D_ / 128, T_ / 8, B_), 128>>>(
        p_hs, p_fds, enc, p_o2, p_o3, output, concat, attn_out);
}

// round 2
// speedup vs baseline: 1.1969x; 1.1969x over previous
#include <cuda_runtime.h>
#include <cuda_bf16.h>
#include <cstdint>

// Shapes (fixed by the problem)
#define B_  4
#define T_  64
#define S_  256
#define E_  512
#define D_  512
#define F_  128

#define LOG2E 1.4426950408889634f

// -------- scratch (device globals; no allocations allowed) --------
__device__ float g_out_hs [S_ * B_ * D_];   // tanh(enc @ W1^T + b1), flat rows
__device__ float g_out_fds[B_ * S_ * D_];   // tanh(z   @ W3^T + b3)
__device__ float g_o2p    [B_ * T_ * D_];   // tanh(out @ W2^T + b2) * log2e
__device__ float g_o3p    [B_ * T_ * D_];   // tanh(out @ W4^T + b4) * log2e

// ============================================================================
// Fused 4-in-1 GEMM, tf32 tensor cores (mma.sync m16n8k8).
// C[M,N] = tanh(A[M,K] @ W[N,K]^T + bias[N]) [* log2e if mode]
// 64x64 tile, BK=32, 256 threads = 8 warps in 4(m) x 2(n); warp tile 16x32.
// All M,N multiples of 64; K multiples of 32.
// ============================================================================
struct Desc {
    const float *A, *W, *bias;
    float *C;
    int K, N, mode;
    int base, bncnt;
};
struct Descs { Desc d[4]; };

__device__ __forceinline__ uint32_t f2tf32(float x) {
    uint32_t r;
    asm("cvt.rna.tf32.f32 %0, %1;" : "=r"(r) : "f"(x));
    return r;
}

__global__ void __launch_bounds__(256, 2)
fused_gemm_tf32(Descs P)
{
    int bx = blockIdx.x;
    int gi;
    if      (bx >= P.d[3].base) gi = 3;
    else if (bx >= P.d[2].base) gi = 2;
    else if (bx >= P.d[1].base) gi = 1;
    else                        gi = 0;
    const Desc dsc = P.d[gi];

    int local = bx - dsc.base;
    int bm = local / dsc.bncnt;
    int bn = local - bm * dsc.bncnt;
    int m0 = bm * 64, n0 = bn * 64;
    const int K = dsc.K, N = dsc.N;

    // padded stride 36 words -> fragment reads are bank-conflict-free
    __shared__ uint32_t As[64][36];
    __shared__ uint32_t Ws[64][36];

    int tid  = threadIdx.x;
    int lane = tid & 31;
    int w    = tid >> 5;
    int wm   = w & 3;          // warp m index 0..3  (16 rows each)
    int wn   = w >> 2;         // warp n index 0..1  (32 cols each)
    int lrow = tid >> 2;       // 0..63 load row
    int lc8  = (tid & 3) * 8;  // 0,8,16,24 load col

    int fr = lane >> 2;        // fragment row / n
    int fc = lane & 3;         // fragment k

    float acc[4][4];
#pragma unroll
    for (int i = 0; i < 4; i++)
#pragma unroll
        for (int j = 0; j < 4; j++) acc[i][j] = 0.f;

    const float* Abase = dsc.A + (size_t)(m0 + lrow) * K + lc8;
    const float* Wbase = dsc.W + (size_t)(n0 + lrow) * K + lc8;

    for (int k0 = 0; k0 < K; k0 += 32) {
        float4 av0 = *(const float4*)(Abase + k0);
        float4 av1 = *(const float4*)(Abase + k0 + 4);
        float4 wv0 = *(const float4*)(Wbase + k0);
        float4 wv1 = *(const float4*)(Wbase + k0 + 4);
        __syncthreads();
        As[lrow][lc8 + 0] = f2tf32(av0.x); As[lrow][lc8 + 1] = f2tf32(av0.y);
        As[lrow][lc8 + 2] = f2tf32(av0.z); As[lrow][lc8 + 3] = f2tf32(av0.w);
        As[lrow][lc8 + 4] = f2tf32(av1.x); As[lrow][lc8 + 5] = f2tf32(av1.y);
        As[lrow][lc8 + 6] = f2tf32(av1.z); As[lrow][lc8 + 7] = f2tf32(av1.w);
        Ws[lrow][lc8 + 0] = f2tf32(wv0.x); Ws[lrow][lc8 + 1] = f2tf32(wv0.y);
        Ws[lrow][lc8 + 2] = f2tf32(wv0.z); Ws[lrow][lc8 + 3] = f2tf32(wv0.w);
        Ws[lrow][lc8 + 4] = f2tf32(wv1.x); Ws[lrow][lc8 + 5] = f2tf32(wv1.y);
        Ws[lrow][lc8 + 6] = f2tf32(wv1.z); Ws[lrow][lc8 + 7] = f2tf32(wv1.w);
        __syncthreads();

#pragma unroll
        for (int ks = 0; ks < 4; ks++) {
            int kc = ks * 8 + fc;
            uint32_t a0 = As[wm * 16 + fr    ][kc];
            uint32_t a1 = As[wm * 16 + fr + 8][kc];
            uint32_t a2 = As[wm * 16 + fr    ][kc + 4];
            uint32_t a3 = As[wm * 16 + fr + 8][kc + 4];
#pragma unroll
            for (int nt = 0; nt < 4; nt++) {
                uint32_t b0 = Ws[wn * 32 + nt * 8 + fr][kc];
                uint32_t b1 = Ws[wn * 32 + nt * 8 + fr][kc + 4];
                asm volatile(
                    "mma.sync.aligned.m16n8k8.row.col.f32.tf32.tf32.f32 "
                    "{%0,%1,%2,%3}, {%4,%5,%6,%7}, {%8,%9}, {%0,%1,%2,%3};"
                    : "+f"(acc[nt][0]), "+f"(acc[nt][1]),
                      "+f"(acc[nt][2]), "+f"(acc[nt][3])
                    : "r"(a0), "r"(a1), "r"(a2), "r"(a3), "r"(b0), "r"(b1));
            }
        }
    }

    // epilogue: bias + tanh (+ *log2e), float2 stores
    int r0 = m0 + wm * 16 + fr;
#pragma unroll
    for (int nt = 0; nt < 4; nt++) {
        int col = n0 + wn * 32 + nt * 8 + 2 * fc;
        float bb0 = dsc.bias[col];
        float bb1 = dsc.bias[col + 1];
        float v0 = tanhf(acc[nt][0] + bb0);
        float v1 = tanhf(acc[nt][1] + bb1);
        float v2 = tanhf(acc[nt][2] + bb0);
        float v3 = tanhf(acc[nt][3] + bb1);
        if (dsc.mode) { v0 *= LOG2E; v1 *= LOG2E; v2 *= LOG2E; v3 *= LOG2E; }
        *(float2*)&dsc.C[(size_t)r0      * N + col] = make_float2(v0, v1);
        *(float2*)&dsc.C[(size_t)(r0 + 8)* N + col] = make_float2(v2, v3);
    }
}

// ============================================================================
// Fused dual-softmax attention (unchanged from R1; math: the two softmaxes'
// normalizers cancel -> softmax_s(h*o2' + f*o3') with base-2 exp).
// ============================================================================
__global__ void __launch_bounds__(128)
dual_attn_kernel(const float* __restrict__ out_hs,
                 const float* __restrict__ out_fds,
                 const float* __restrict__ enc,
                 const float* __restrict__ o2p,
                 const float* __restrict__ o3p,
                 const float* __restrict__ outp,
                 float* __restrict__ concat,
                 float* __restrict__ attn_out)
{
    const int TT = 8;
    int d  = blockIdx.x * 128 + threadIdx.x;
    int t0 = blockIdx.y * TT;
    int b  = blockIdx.z;

    float o2[TT], o3[TT], s1[TT], s2[TT];
#pragma unroll
    for (int i = 0; i < TT; i++) {
        int r = b * T_ + t0 + i;
        o2[i] = o2p[r * D_ + d];
        o3[i] = o3p[r * D_ + d];
        s1[i] = 0.f;
        s2[i] = 0.f;
    }

    size_t base = (size_t)(b * S_) * D_ + d;
#pragma unroll 2
    for (int s = 0; s < S_; s++) {
        float h = out_hs [base];
        float f = out_fds[base];
        float e = enc    [base];
        base += D_;
#pragma unroll
        for (int i = 0; i < TT; i++) {
            float g = fmaf(h, o2[i], f * o3[i]);
            float ex;
            asm("ex2.approx.f32 %0, %1;" : "=f"(ex) : "f"(g));
            s1[i] += ex;
            s2[i] = fmaf(ex, e, s2[i]);
        }
    }

#pragma unroll
    for (int i = 0; i < TT; i++) {
        int r = b * T_ + t0 + i;
        float a = s2[i] / s1[i];
        concat[(size_t)r * (2 * D_) + d]      = outp[(size_t)r * D_ + d];
        concat[(size_t)r * (2 * D_) + D_ + d] = a;
        if (attn_out) attn_out[(size_t)r * D_ + d] = a;
    }
}

// ============================================================================
// kernel_launch
// ============================================================================
extern "C" void kernel_launch(void* const* d_in, const int* in_sizes, int n_in,
                              void* d_out, int out_size)
{
    const float* output = (const float*)d_in[0];
    const float* enc    = (const float*)d_in[1];
    const float* z      = (const float*)d_in[2];
    const float* W1 = (const float*)d_in[3];
    const float* b1 = (const float*)d_in[4];
    const float* W2 = (const float*)d_in[5];
    const float* b2 = (const float*)d_in[6];
    const float* W3 = (const float*)d_in[7];
    const float* b3 = (const float*)d_in[8];
    const float* W4 = (const float*)d_in[9];
    const float* b4 = (const float*)d_in[10];

    float *p_hs, *p_fds, *p_o2, *p_o3;
    cudaGetSymbolAddress((void**)&p_hs,  g_out_hs);
    cudaGetSymbolAddress((void**)&p_fds, g_out_fds);
    cudaGetSymbolAddress((void**)&p_o2,  g_o2p);
    cudaGetSymbolAddress((void**)&p_o3,  g_o3p);

    float* concat = (float*)d_out;
    const int concat_elems = B_ * T_ * 2 * D_;
    const int attn_elems   = B_ * T_ * D_;
    float* attn_out = (out_size >= concat_elems + attn_elems)
                        ? concat + concat_elems : nullptr;

    // block counts: lin1 16x8=128, lin3 16x8=128, lin2 4x8=32, lin4 4x8=32
    Descs P;
    P.d[0] = { enc,    W1, b1, p_hs,  E_, D_, 0,   0, D_ / 64 };
    P.d[1] = { z,      W3, b3, p_fds, F_, D_, 0, 128, D_ / 64 };
    P.d[2] = { output, W2, b2, p_o2,  D_, D_, 1, 256, D_ / 64 };
    P.d[3] = { output, W4, b4, p_o3,  D_, D_, 1, 288, D_ / 64 };

    fused_gemm_tf32<<<320, 256>>>(P);

    dual_attn_kernel<<<dim3(D_ / 128, T_ / 8, B_), 128>>>(
        p_hs, p_fds, enc, p_o2, p_o3, output, concat, attn_out);
}

// round 3
// speedup vs baseline: 1.8182x; 1.5191x over previous
#include <cuda_runtime.h>
#include <cuda_bf16.h>
#include <cstdint>

#define B_  4
#define T_  64
#define S_  256
#define E_  512
#define D_  512
#define F_  128

#define LOG2E 1.4426950408889634f
#define SCH 4              // S-chunks for attention parallelism
#define TT  8              // decoder steps per attention block

// -------- scratch (device globals) --------
__device__ float g_out_hs [S_ * B_ * D_];
__device__ float g_out_fds[B_ * S_ * D_];
__device__ float g_o2p    [B_ * T_ * D_];
__device__ float g_o3p    [B_ * T_ * D_];
__device__ float g_ps1    [B_ * T_ * SCH * D_];   // partial softmax denom
__device__ float g_ps2    [B_ * T_ * SCH * D_];   // partial weighted sum

// ============================================================================
// Fused 4-in-1 GEMM, tf32 tensor cores (unchanged from R2 — it works).
// ============================================================================
struct Desc {
    const float *A, *W, *bias;
    float *C;
    int K, N, mode;
    int base, bncnt;
};
struct Descs { Desc d[4]; };

__device__ __forceinline__ uint32_t f2tf32(float x) {
    uint32_t r;
    asm("cvt.rna.tf32.f32 %0, %1;" : "=r"(r) : "f"(x));
    return r;
}

__global__ void __launch_bounds__(256, 2)
fused_gemm_tf32(Descs P)
{
    int bx = blockIdx.x;
    int gi;
    if      (bx >= P.d[3].base) gi = 3;
    else if (bx >= P.d[2].base) gi = 2;
    else if (bx >= P.d[1].base) gi = 1;
    else                        gi = 0;
    const Desc dsc = P.d[gi];

    int local = bx - dsc.base;
    int bm = local / dsc.bncnt;
    int bn = local - bm * dsc.bncnt;
    int m0 = bm * 64, n0 = bn * 64;
    const int K = dsc.K, N = dsc.N;

    __shared__ uint32_t As[64][36];
    __shared__ uint32_t Ws[64][36];

    int tid  = threadIdx.x;
    int lane = tid & 31;
    int w    = tid >> 5;
    int wm   = w & 3;
    int wn   = w >> 2;
    int lrow = tid >> 2;
    int lc8  = (tid & 3) * 8;

    int fr = lane >> 2;
    int fc = lane & 3;

    float acc[4][4];
#pragma unroll
    for (int i = 0; i < 4; i++)
#pragma unroll
        for (int j = 0; j < 4; j++) acc[i][j] = 0.f;

    const float* Abase = dsc.A + (size_t)(m0 + lrow) * K + lc8;
    const float* Wbase = dsc.W + (size_t)(n0 + lrow) * K + lc8;

    for (int k0 = 0; k0 < K; k0 += 32) {
        float4 av0 = *(const float4*)(Abase + k0);
        float4 av1 = *(const float4*)(Abase + k0 + 4);
        float4 wv0 = *(const float4*)(Wbase + k0);
        float4 wv1 = *(const float4*)(Wbase + k0 + 4);
        __syncthreads();
        As[lrow][lc8 + 0] = f2tf32(av0.x); As[lrow][lc8 + 1] = f2tf32(av0.y);
        As[lrow][lc8 + 2] = f2tf32(av0.z); As[lrow][lc8 + 3] = f2tf32(av0.w);
        As[lrow][lc8 + 4] = f2tf32(av1.x); As[lrow][lc8 + 5] = f2tf32(av1.y);
        As[lrow][lc8 + 6] = f2tf32(av1.z); As[lrow][lc8 + 7] = f2tf32(av1.w);
        Ws[lrow][lc8 + 0] = f2tf32(wv0.x); Ws[lrow][lc8 + 1] = f2tf32(wv0.y);
        Ws[lrow][lc8 + 2] = f2tf32(wv0.z); Ws[lrow][lc8 + 3] = f2tf32(wv0.w);
        Ws[lrow][lc8 + 4] = f2tf32(wv1.x); Ws[lrow][lc8 + 5] = f2tf32(wv1.y);
        Ws[lrow][lc8 + 6] = f2tf32(wv1.z); Ws[lrow][lc8 + 7] = f2tf32(wv1.w);
        __syncthreads();

#pragma unroll
        for (int ks = 0; ks < 4; ks++) {
            int kc = ks * 8 + fc;
            uint32_t a0 = As[wm * 16 + fr    ][kc];
            uint32_t a1 = As[wm * 16 + fr + 8][kc];
            uint32_t a2 = As[wm * 16 + fr    ][kc + 4];
            uint32_t a3 = As[wm * 16 + fr + 8][kc + 4];
#pragma unroll
            for (int nt = 0; nt < 4; nt++) {
                uint32_t b0 = Ws[wn * 32 + nt * 8 + fr][kc];
                uint32_t b1 = Ws[wn * 32 + nt * 8 + fr][kc + 4];
                asm volatile(
                    "mma.sync.aligned.m16n8k8.row.col.f32.tf32.tf32.f32 "
                    "{%0,%1,%2,%3}, {%4,%5,%6,%7}, {%8,%9}, {%0,%1,%2,%3};"
                    : "+f"(acc[nt][0]), "+f"(acc[nt][1]),
                      "+f"(acc[nt][2]), "+f"(acc[nt][3])
                    : "r"(a0), "r"(a1), "r"(a2), "r"(a3), "r"(b0), "r"(b1));
            }
        }
    }

    int r0 = m0 + wm * 16 + fr;
#pragma unroll
    for (int nt = 0; nt < 4; nt++) {
        int col = n0 + wn * 32 + nt * 8 + 2 * fc;
        float bb0 = dsc.bias[col];
        float bb1 = dsc.bias[col + 1];
        float v0 = tanhf(acc[nt][0] + bb0);
        float v1 = tanhf(acc[nt][1] + bb1);
        float v2 = tanhf(acc[nt][2] + bb0);
        float v3 = tanhf(acc[nt][3] + bb1);
        if (dsc.mode) { v0 *= LOG2E; v1 *= LOG2E; v2 *= LOG2E; v3 *= LOG2E; }
        *(float2*)&dsc.C[(size_t)r0      * N + col] = make_float2(v0, v1);
        *(float2*)&dsc.C[(size_t)(r0 + 8)* N + col] = make_float2(v2, v3);
    }
}

// ============================================================================
// Attention partial: each block handles one (b, t-tile, d-chunk, s-chunk).
// s1,s2 partials over 64 encoder positions -> scratch.
// Grid: x = d-chunk (4), y = t-tile (8), z = b*SCH+sc (16)  -> 512 blocks.
// Loads batched 4 s-steps ahead (MLP ~12).
// ============================================================================
__global__ void __launch_bounds__(128)
dual_attn_partial(const float* __restrict__ out_hs,
                  const float* __restrict__ out_fds,
                  const float* __restrict__ enc,
                  const float* __restrict__ o2p,
                  const float* __restrict__ o3p,
                  float* __restrict__ ps1,
                  float* __restrict__ ps2)
{
    int d  = blockIdx.x * 128 + threadIdx.x;
    int t0 = blockIdx.y * TT;
    int bz = blockIdx.z;
    int b  = bz >> 2;
    int sc = bz & 3;

    float o2[TT], o3[TT], s1[TT], s2[TT];
#pragma unroll
    for (int i = 0; i < TT; i++) {
        int r = b * T_ + t0 + i;
        o2[i] = o2p[r * D_ + d];
        o3[i] = o3p[r * D_ + d];
        s1[i] = 0.f;
        s2[i] = 0.f;
    }

    const int SC = S_ / SCH;   // 64
    size_t base = ((size_t)b * S_ + sc * SC) * D_ + d;

    for (int s = 0; s < SC; s += 4) {
        float h0 = out_hs [base],          h1 = out_hs [base + D_];
        float h2 = out_hs [base + 2 * D_], h3 = out_hs [base + 3 * D_];
        float f0 = out_fds[base],          f1 = out_fds[base + D_];
        float f2 = out_fds[base + 2 * D_], f3 = out_fds[base + 3 * D_];
        float e0 = enc    [base],          e1 = enc    [base + D_];
        float e2 = enc    [base + 2 * D_], e3 = enc    [base + 3 * D_];
        base += 4 * D_;
        float hh[4] = {h0, h1, h2, h3};
        float ff[4] = {f0, f1, f2, f3};
        float ee[4] = {e0, e1, e2, e3};
#pragma unroll
        for (int u = 0; u < 4; u++) {
#pragma unroll
            for (int i = 0; i < TT; i++) {
                float g = fmaf(hh[u], o2[i], ff[u] * o3[i]);
                float ex;
                asm("ex2.approx.f32 %0, %1;" : "=f"(ex) : "f"(g));
                s1[i] += ex;
                s2[i] = fmaf(ex, ee[u], s2[i]);
            }
        }
    }

#pragma unroll
    for (int i = 0; i < TT; i++) {
        size_t idx = (((size_t)(b * T_ + t0 + i)) * SCH + sc) * D_ + d;
        ps1[idx] = s1[i];
        ps2[idx] = s2[i];
    }
}

// ============================================================================
// Finalize: reduce SCH partials, divide, write concat (+attn).
// Grid: x = d-chunk (4), y = t (64), z = b (4). 128 threads.
// ============================================================================
__global__ void __launch_bounds__(128)
attn_finalize(const float* __restrict__ ps1,
              const float* __restrict__ ps2,
              const float* __restrict__ outp,
              float* __restrict__ concat,
              float* __restrict__ attn_out)
{
    int d = blockIdx.x * 128 + threadIdx.x;
    int r = blockIdx.z * T_ + blockIdx.y;

    size_t base = ((size_t)r * SCH) * D_ + d;
    float s1 = 0.f, s2 = 0.f;
#pragma unroll
    for (int sc = 0; sc < SCH; sc++) {
        s1 += ps1[base + sc * D_];
        s2 += ps2[base + sc * D_];
    }
    float a = s2 / s1;
    concat[(size_t)r * (2 * D_) + d]      = outp[(size_t)r * D_ + d];
    concat[(size_t)r * (2 * D_) + D_ + d] = a;
    if (attn_out) attn_out[(size_t)r * D_ + d] = a;
}

// ============================================================================
// kernel_launch
// ============================================================================
extern "C" void kernel_launch(void* const* d_in, const int* in_sizes, int n_in,
                              void* d_out, int out_size)
{
    const float* output = (const float*)d_in[0];
    const float* enc    = (const float*)d_in[1];
    const float* z      = (const float*)d_in[2];
    const float* W1 = (const float*)d_in[3];
    const float* b1 = (const float*)d_in[4];
    const float* W2 = (const float*)d_in[5];
    const float* b2 = (const float*)d_in[6];
    const float* W3 = (const float*)d_in[7];
    const float* b3 = (const float*)d_in[8];
    const float* W4 = (const float*)d_in[9];
    const float* b4 = (const float*)d_in[10];

    float *p_hs, *p_fds, *p_o2, *p_o3, *p_s1, *p_s2;
    cudaGetSymbolAddress((void**)&p_hs,  g_out_hs);
    cudaGetSymbolAddress((void**)&p_fds, g_out_fds);
    cudaGetSymbolAddress((void**)&p_o2,  g_o2p);
    cudaGetSymbolAddress((void**)&p_o3,  g_o3p);
    cudaGetSymbolAddress((void**)&p_s1,  g_ps1);
    cudaGetSymbolAddress((void**)&p_s2,  g_ps2);

    float* concat = (float*)d_out;
    const int concat_elems = B_ * T_ * 2 * D_;
    const int attn_elems   = B_ * T_ * D_;
    float* attn_out = (out_size >= concat_elems + attn_elems)
                        ? concat + concat_elems : nullptr;

    Descs P;
    P.d[0] = { enc,    W1, b1, p_hs,  E_, D_, 0,   0, D_ / 64 };
    P.d[1] = { z,      W3, b3, p_fds, F_, D_, 0, 128, D_ / 64 };
    P.d[2] = { output, W2, b2, p_o2,  D_, D_, 1, 256, D_ / 64 };
    P.d[3] = { output, W4, b4, p_o3,  D_, D_, 1, 288, D_ / 64 };

    fused_gemm_tf32<<<320, 256>>>(P);

    dual_attn_partial<<<dim3(D_ / 128, T_ / TT, B_ * SCH), 128>>>(
        p_hs, p_fds, enc, p_o2, p_o3, p_s1, p_s2);

    attn_finalize<<<dim3(D_ / 128, T_, B_), 128>>>(
        p_s1, p_s2, output, concat, attn_out);
}

// round 4
// speedup vs baseline: 2.8472x; 1.5659x over previous
#include <cuda_runtime.h>
#include <cuda_bf16.h>
#include <cstdint>

#define B_  4
#define T_  64
#define S_  256
#define E_  512
#define D_  512
#define F_  128

#define LOG2E 1.4426950408889634f
#define SCH 8              // S-chunks for attention parallelism
#define TT  8              // decoder steps per attention block

// -------- scratch (device globals) --------
__device__ float g_out_hs [S_ * B_ * D_];
__device__ float g_out_fds[B_ * S_ * D_];
__device__ float g_o2p    [B_ * T_ * D_];
__device__ float g_o3p    [B_ * T_ * D_];
__device__ float g_ps1    [B_ * T_ * SCH * D_];
__device__ float g_ps2    [B_ * T_ * SCH * D_];

// ============================================================================
// Fused 4-in-1 GEMM, tf32 mma.sync, register-prefetch pipelined,
// conflict-free vectorized smem stores.
// ============================================================================
struct Desc {
    const float *A, *W, *bias;
    float *C;
    int K, N, mode;
    int base, bncnt;
};
struct Descs { Desc d[4]; };

__device__ __forceinline__ uint32_t f2tf32(float x) {
    uint32_t r;
    asm("cvt.rna.tf32.f32 %0, %1;" : "=r"(r) : "f"(x));
    return r;
}
__device__ __forceinline__ uint4 cvt4(float4 v) {
    uint4 u;
    u.x = f2tf32(v.x); u.y = f2tf32(v.y); u.z = f2tf32(v.z); u.w = f2tf32(v.w);
    return u;
}

__global__ void __launch_bounds__(256, 3)
fused_gemm_tf32(Descs P)
{
    int bx = blockIdx.x;
    int gi;
    if      (bx >= P.d[3].base) gi = 3;
    else if (bx >= P.d[2].base) gi = 2;
    else if (bx >= P.d[1].base) gi = 1;
    else                        gi = 0;
    const Desc dsc = P.d[gi];

    int local = bx - dsc.base;
    int bm = local / dsc.bncnt;
    int bn = local - bm * dsc.bncnt;
    int m0 = bm * 64, n0 = bn * 64;
    const int K = dsc.K, N = dsc.N;

    // stride 36: fragment reads CF (bank = 4*fr+fc = lane), uint4 stores CF.
    __shared__ uint32_t As[64][36];
    __shared__ uint32_t Ws[64][36];

    int tid  = threadIdx.x;
    int lane = tid & 31;
    int w    = tid >> 5;
    int wm   = w & 3;
    int wn   = w >> 2;
    int lrow = tid >> 2;
    int lc8  = (tid & 3) * 8;

    int fr = lane >> 2;
    int fc = lane & 3;

    float acc[4][4];
#pragma unroll
    for (int i = 0; i < 4; i++)
#pragma unroll
        for (int j = 0; j < 4; j++) acc[i][j] = 0.f;

    const float* Abase = dsc.A + (size_t)(m0 + lrow) * K + lc8;
    const float* Wbase = dsc.W + (size_t)(n0 + lrow) * K + lc8;

    int nk = K >> 5;
    // prefetch chunk 0 into registers
    float4 ra0 = *(const float4*)(Abase);
    float4 ra1 = *(const float4*)(Abase + 4);
    float4 rw0 = *(const float4*)(Wbase);
    float4 rw1 = *(const float4*)(Wbase + 4);

    for (int ks = 0; ks < nk; ks++) {
        __syncthreads();   // all warps done reading previous chunk
        *(uint4*)&As[lrow][lc8]     = cvt4(ra0);
        *(uint4*)&As[lrow][lc8 + 4] = cvt4(ra1);
        *(uint4*)&Ws[lrow][lc8]     = cvt4(rw0);
        *(uint4*)&Ws[lrow][lc8 + 4] = cvt4(rw1);
        __syncthreads();

        if (ks + 1 < nk) {          // prefetch next chunk; latency hidden by MMAs
            const float* ap = Abase + ((ks + 1) << 5);
            const float* wp = Wbase + ((ks + 1) << 5);
            ra0 = *(const float4*)(ap);
            ra1 = *(const float4*)(ap + 4);
            rw0 = *(const float4*)(wp);
            rw1 = *(const float4*)(wp + 4);
        }

#pragma unroll
        for (int kq = 0; kq < 4; kq++) {
            int kc = kq * 8 + fc;
            uint32_t a0 = As[wm * 16 + fr    ][kc];
            uint32_t a1 = As[wm * 16 + fr + 8][kc];
            uint32_t a2 = As[wm * 16 + fr    ][kc + 4];
            uint32_t a3 = As[wm * 16 + fr + 8][kc + 4];
#pragma unroll
            for (int nt = 0; nt < 4; nt++) {
                uint32_t b0 = Ws[wn * 32 + nt * 8 + fr][kc];
                uint32_t b1 = Ws[wn * 32 + nt * 8 + fr][kc + 4];
                asm volatile(
                    "mma.sync.aligned.m16n8k8.row.col.f32.tf32.tf32.f32 "
                    "{%0,%1,%2,%3}, {%4,%5,%6,%7}, {%8,%9}, {%0,%1,%2,%3};"
                    : "+f"(acc[nt][0]), "+f"(acc[nt][1]),
                      "+f"(acc[nt][2]), "+f"(acc[nt][3])
                    : "r"(a0), "r"(a1), "r"(a2), "r"(a3), "r"(b0), "r"(b1));
            }
        }
    }

    int r0 = m0 + wm * 16 + fr;
#pragma unroll
    for (int nt = 0; nt < 4; nt++) {
        int col = n0 + wn * 32 + nt * 8 + 2 * fc;
        float bb0 = dsc.bias[col];
        float bb1 = dsc.bias[col + 1];
        float v0 = tanhf(acc[nt][0] + bb0);
        float v1 = tanhf(acc[nt][1] + bb1);
        float v2 = tanhf(acc[nt][2] + bb0);
        float v3 = tanhf(acc[nt][3] + bb1);
        if (dsc.mode) { v0 *= LOG2E; v1 *= LOG2E; v2 *= LOG2E; v3 *= LOG2E; }
        *(float2*)&dsc.C[(size_t)r0       * N + col] = make_float2(v0, v1);
        *(float2*)&dsc.C[(size_t)(r0 + 8) * N + col] = make_float2(v2, v3);
    }
}

// ============================================================================
// Attention partial over S/SCH = 32 encoder positions per block.
// Grid: x = d-chunk (4), y = t-tile (8), z = b*SCH+sc (32) -> 1024 blocks.
// ============================================================================
__global__ void __launch_bounds__(128)
dual_attn_partial(const float* __restrict__ out_hs,
                  const float* __restrict__ out_fds,
                  const float* __restrict__ enc,
                  const float* __restrict__ o2p,
                  const float* __restrict__ o3p,
                  float* __restrict__ ps1,
                  float* __restrict__ ps2)
{
    int d  = blockIdx.x * 128 + threadIdx.x;
    int t0 = blockIdx.y * TT;
    int bz = blockIdx.z;
    int b  = bz >> 3;
    int sc = bz & 7;

    float o2[TT], o3[TT], s1[TT], s2[TT];
#pragma unroll
    for (int i = 0; i < TT; i++) {
        int r = b * T_ + t0 + i;
        o2[i] = o2p[r * D_ + d];
        o3[i] = o3p[r * D_ + d];
        s1[i] = 0.f;
        s2[i] = 0.f;
    }

    const int SC = S_ / SCH;   // 32
    size_t base = ((size_t)b * S_ + sc * SC) * D_ + d;

    for (int s = 0; s < SC; s += 4) {
        float hh[4], ff[4], ee[4];
#pragma unroll
        for (int u = 0; u < 4; u++) hh[u] = out_hs [base + u * D_];
#pragma unroll
        for (int u = 0; u < 4; u++) ff[u] = out_fds[base + u * D_];
#pragma unroll
        for (int u = 0; u < 4; u++) ee[u] = enc    [base + u * D_];
        base += 4 * D_;
#pragma unroll
        for (int u = 0; u < 4; u++) {
#pragma unroll
            for (int i = 0; i < TT; i++) {
                float g = fmaf(hh[u], o2[i], ff[u] * o3[i]);
                float ex;
                asm("ex2.approx.f32 %0, %1;" : "=f"(ex) : "f"(g));
                s1[i] += ex;
                s2[i] = fmaf(ex, ee[u], s2[i]);
            }
        }
    }

#pragma unroll
    for (int i = 0; i < TT; i++) {
        size_t idx = (((size_t)(b * T_ + t0 + i)) * SCH + sc) * D_ + d;
        ps1[idx] = s1[i];
        ps2[idx] = s2[i];
    }
}

// ============================================================================
// Finalize: reduce SCH partials (float4), divide, write concat (+attn).
// Grid: (1, T_, B_), 128 threads, 4 d per thread.
// ============================================================================
__global__ void __launch_bounds__(128)
attn_finalize(const float* __restrict__ ps1,
              const float* __restrict__ ps2,
              const float* __restrict__ outp,
              float* __restrict__ concat,
              float* __restrict__ attn_out)
{
    int d4 = threadIdx.x * 4;
    int r  = blockIdx.z * T_ + blockIdx.y;

    size_t base = ((size_t)r * SCH) * D_ + d4;
    float4 s1 = make_float4(0, 0, 0, 0), s2 = make_float4(0, 0, 0, 0);
#pragma unroll
    for (int sc = 0; sc < SCH; sc++) {
        float4 a = *(const float4*)&ps1[base + (size_t)sc * D_];
        float4 b = *(const float4*)&ps2[base + (size_t)sc * D_];
        s1.x += a.x; s1.y += a.y; s1.z += a.z; s1.w += a.w;
        s2.x += b.x; s2.y += b.y; s2.z += b.z; s2.w += b.w;
    }
    float4 at = make_float4(s2.x / s1.x, s2.y / s1.y, s2.z / s1.z, s2.w / s1.w);
    float4 ov = *(const float4*)&outp[(size_t)r * D_ + d4];
    *(float4*)&concat[(size_t)r * (2 * D_) + d4]      = ov;
    *(float4*)&concat[(size_t)r * (2 * D_) + D_ + d4] = at;
    if (attn_out) *(float4*)&attn_out[(size_t)r * D_ + d4] = at;
}

// ============================================================================
// kernel_launch
// ============================================================================
extern "C" void kernel_launch(void* const* d_in, const int* in_sizes, int n_in,
                              void* d_out, int out_size)
{
    const float* output = (const float*)d_in[0];
    const float* enc    = (const float*)d_in[1];
    const float* z      = (const float*)d_in[2];
    const float* W1 = (const float*)d_in[3];
    const float* b1 = (const float*)d_in[4];
    const float* W2 = (const float*)d_in[5];
    const float* b2 = (const float*)d_in[6];
    const float* W3 = (const float*)d_in[7];
    const float* b3 = (const float*)d_in[8];
    const float* W4 = (const float*)d_in[9];
    const float* b4 = (const float*)d_in[10];

    float *p_hs, *p_fds, *p_o2, *p_o3, *p_s1, *p_s2;
    cudaGetSymbolAddress((void**)&p_hs,  g_out_hs);
    cudaGetSymbolAddress((void**)&p_fds, g_out_fds);
    cudaGetSymbolAddress((void**)&p_o2,  g_o2p);
    cudaGetSymbolAddress((void**)&p_o3,  g_o3p);
    cudaGetSymbolAddress((void**)&p_s1,  g_ps1);
    cudaGetSymbolAddress((void**)&p_s2,  g_ps2);

    float* concat = (float*)d_out;
    const int concat_elems = B_ * T_ * 2 * D_;
    const int attn_elems   = B_ * T_ * D_;
    float* attn_out = (out_size >= concat_elems + attn_elems)
                        ? concat + concat_elems : nullptr;

    Descs P;
    P.d[0] = { enc,    W1, b1, p_hs,  E_, D_, 0,   0, D_ / 64 };
    P.d[1] = { z,      W3, b3, p_fds, F_, D_, 0, 128, D_ / 64 };
    P.d[2] = { output, W2, b2, p_o2,  D_, D_, 1, 256, D_ / 64 };
    P.d[3] = { output, W4, b4, p_o3,  D_, D_, 1, 288, D_ / 64 };

    fused_gemm_tf32<<<320, 256>>>(P);

    dual_attn_partial<<<dim3(D_ / 128, T_ / TT, B_ * SCH), 128>>>(
        p_hs, p_fds, enc, p_o2, p_o3, p_s1, p_s2);

    attn_finalize<<<dim3(1, T_, B_), 128>>>(
        p_s1, p_s2, output, concat, attn_out);
}